// round 15
// baseline (speedup 1.0000x reference)
#include <cuda_runtime.h>

// Node2VecModel: N=6, EMB=32. TWO independent CTAs (one chain per SM):
//   block 0 (192 thr): energy MLP -> out[0..5]
//   block 1 ( 64 thr): raw path logits -> gumbel-max walk -> out[6..12]
// R15 = R13 (measured best) + pure instruction-count cuts, values unchanged:
//   float4 x staging (48 LDG.128), LDS.128 reads in h1 and h2 (same k order).
// Invariants (measured): weights in registers; baked threefry+gumbel consts;
//   raw-logit argmax; smem walk on one thread; 2-CTA chain separation.

#define NN   6
#define EMBD 32
#define H1   64
#define H2   32

// ---------------- compile-time threefry2x32 (partitionable JAX path) ----------------
struct TF2 { unsigned a, b; };

constexpr unsigned rotl_c(unsigned x, int r) { return (x << r) | (x >> (32 - r)); }

constexpr TF2 tf_const(unsigned k0, unsigned k1, unsigned x0, unsigned x1) {
    unsigned ks2 = k0 ^ k1 ^ 0x1BD11BDAu;
    x0 += k0; x1 += k1;
#define TFC(r) { x0 += x1; x1 = rotl_c(x1, r); x1 ^= x0; }
    TFC(13) TFC(15) TFC(26) TFC(6)
    x0 += k1;  x1 += ks2 + 1u;
    TFC(17) TFC(29) TFC(16) TFC(24)
    x0 += ks2; x1 += k0 + 2u;
    TFC(13) TFC(15) TFC(26) TFC(6)
    x0 += k0;  x1 += k1 + 3u;
    TFC(17) TFC(29) TFC(16) TFC(24)
    x0 += k1;  x1 += ks2 + 4u;
    TFC(13) TFC(15) TFC(26) TFC(6)
    x0 += ks2; x1 += k0 + 5u;
#undef TFC
    return TF2{x0, x1};
}

// split(key(42),5)[s] = tf((0,42),(0,s)); bits[j] = o0^o1 of tf(key,(0,j))
constexpr unsigned gbits(unsigned s, unsigned j) {
    TF2 key = tf_const(0u, 42u, 0u, s);
    TF2 o   = tf_const(key.a, key.b, 0u, j);
    return o.a ^ o.b;
}

// compile-time natural log (double): v = m*2^e, m in [0.5,1);
// ln(m) = 2*atanh((m-1)/(m+1)) series. |err| ~ 1e-16.
constexpr double clog(double v) {
    int e = 0;
    while (v >= 1.0) { v *= 0.5; e++; }
    while (v < 0.5)  { v *= 2.0; e--; }
    double t = (v - 1.0) / (v + 1.0);
    double t2 = t * t, term = t, sum = 0.0;
    for (int i = 1; i < 61; i += 2) { sum += term / (double)i; term *= t2; }
    return 2.0 * sum + (double)e * 0.6931471805599453;
}

// gumbel value from threefry bits, fully compile time. Matches device math:
// f = (b>>9)/2^23 (exact), u = max(tiny, f+tiny), g = -log(-log(u)).
// Gumbel gaps are O(0.1); 1e-7-scale differences cannot flip the argmax.
constexpr float gumbel_c(unsigned b) {
    const double tiny = 1.1754943508222875e-38;
    double f = (double)(b >> 9) / 8388608.0;
    double u = f + tiny;
    if (u < tiny) u = tiny;
    return (float)(-clog(-clog(u)));
}

#define GBV(s) gumbel_c(gbits(s,0)), gumbel_c(gbits(s,1)), gumbel_c(gbits(s,2)), \
               gumbel_c(gbits(s,3)), gumbel_c(gbits(s,4)), gumbel_c(gbits(s,5))
__device__ constexpr float GVAL[(NN - 1) * NN] = { GBV(0), GBV(1), GBV(2), GBV(3), GBV(4) };
#undef GBV

__global__ __launch_bounds__(192, 1)
void node2vec_kernel(const float* __restrict__ x,
                     const float* __restrict__ fc1_w, const float* __restrict__ fc1_b,
                     const float* __restrict__ fc2_w, const float* __restrict__ fc2_b,
                     const float* __restrict__ fc3_w, const float* __restrict__ fc3_b,
                     const float* __restrict__ pw,    const float* __restrict__ pb,
                     float* __restrict__ out) {
    __shared__ float sxE[NN * EMBD];         // block 0: staged x (16B aligned)
    __shared__ float h1s[NN][H1];            // block 0: h1 (rows 256B aligned)
    __shared__ float logits[NN][NN];         // block 1: raw logits

    int tid = threadIdx.x;

    if (blockIdx.x == 0) {
        // ================= ENERGY CTA (192 thr, own SM) =================
        int j1 = tid & 63, r1 = tid >> 6;          // h1 elems (r1,j1),(r1+3,j1)
        int i2 = tid >> 5, j2 = tid & 31;          // h2 elem (i2,j2); warp i2 = row i2

        // register prefetch: all LDGs issued before the first barrier
        float w1[EMBD];
        #pragma unroll
        for (int k = 0; k < EMBD; k++) w1[k] = fc1_w[k * H1 + j1];
        float b1v = fc1_b[j1];

        float w2[H1];
        #pragma unroll
        for (int k = 0; k < H1; k++) w2[k] = fc2_w[k * H2 + j2];
        float b2v = fc2_b[j2];
        float w3v = fc3_w[j2];
        float b3v = fc3_b[0];

        // stage x via float4: 48 LDG.128 total (same bytes as R13's 192 scalars)
        if (tid < 48) ((float4*)sxE)[tid] = ((const float4*)x)[tid];
        __syncthreads();

        // h1 = relu(x @ fc1_w + b1): 2 rows/thread, 4-way split accumulators.
        // LDS.128 reads; component->k mapping identical to R13 (values unchanged).
        {
            float p0 = 0.f, p1 = 0.f, p2 = 0.f, p3 = 0.f;
            float q0 = 0.f, q1 = 0.f, q2 = 0.f, q3 = 0.f;
            #pragma unroll
            for (int k = 0; k < EMBD; k += 4) {
                float4 va = *(const float4*)&sxE[r1 * EMBD + k];
                float4 vb = *(const float4*)&sxE[(r1 + 3) * EMBD + k];
                p0 += va.x * w1[k];
                p1 += va.y * w1[k + 1];
                p2 += va.z * w1[k + 2];
                p3 += va.w * w1[k + 3];
                q0 += vb.x * w1[k];
                q1 += vb.y * w1[k + 1];
                q2 += vb.z * w1[k + 2];
                q3 += vb.w * w1[k + 3];
            }
            h1s[r1][j1]     = fmaxf(b1v + ((p0 + p1) + (p2 + p3)), 0.0f);
            h1s[r1 + 3][j1] = fmaxf(b1v + ((q0 + q1) + (q2 + q3)), 0.0f);
        }
        __syncthreads();

        // h2 + energy head fused: warp i2 owns row i2; LDS.128 broadcast reads
        // of the shared h1 row (all lanes same address: conflict-free).
        {
            float c0 = 0.f, c1 = 0.f, c2 = 0.f, c3 = 0.f;
            #pragma unroll
            for (int k = 0; k < H1; k += 4) {
                float4 hv = *(const float4*)&h1s[i2][k];
                c0 += hv.x * w2[k];
                c1 += hv.y * w2[k + 1];
                c2 += hv.z * w2[k + 2];
                c3 += hv.w * w2[k + 3];
            }
            float rel = fmaxf(b2v + ((c0 + c1) + (c2 + c3)), 0.0f);
            float p = rel * w3v;
            #pragma unroll
            for (int off = 16; off; off >>= 1)
                p += __shfl_xor_sync(0xffffffffu, p, off);
            if (j2 == 0) {
                float acc = p + b3v;
                out[i2] = fmaxf(acc, 0.0f) + log1pf(expf(-fabsf(acc)));  // softplus
            }
        }
    } else {
        // ================= PATH CTA (64 of 192 thr, own SM) — identical R13 =========
        if (tid >= 64) return;
        int t = tid;

        // fixed endpoints: write early from an otherwise-idle thread
        if (t == 40) { out[NN] = 0.0f; out[2 * NN] = 0.0f; }

        // raw logits = x @ path_fc_w + path_fc_b (36 threads) — LDG-bound.
        // log_softmax skipped: per-row constant cancels in the argmax below.
        if (t < NN * NN) {
            int i = t / NN, j = t % NN;
            float acc = pb[j];
            #pragma unroll
            for (int k = 0; k < EMBD; k++)
                acc += x[i * EMBD + k] * pw[k * NN + j];
            logits[i][j] = acc;
        }
        asm volatile("bar.sync 2, 64;" ::: "memory");

        // serial gumbel-max walk (thread 0): gumbels are immediates,
        // per step just 6 LDS + compares.
        if (t == 0) {
            bool mask[NN];
            mask[0] = false;
            #pragma unroll
            for (int j = 1; j < NN; j++) mask[j] = true;

            int cur = 0;
            #pragma unroll
            for (int step = 0; step < NN - 1; step++) {
                float best = -__int_as_float(0x7f800000);
                int bestj = 0;
                bool have = false;
                #pragma unroll
                for (int j = 0; j < NN; j++) {
                    if (!mask[j]) continue;          // where(mask,.,-inf)+g = -inf
                    float v = logits[cur][j] + GVAL[step * NN + j];
                    if (!have || v > best) { best = v; bestj = j; have = true; }
                }
                cur = bestj;
                mask[bestj] = false;
                out[NN + 1 + step] = (float)bestj;
            }
        }
    }
}

extern "C" void kernel_launch(void* const* d_in, const int* in_sizes, int n_in,
                              void* d_out, int out_size) {
    const float* x     = (const float*)d_in[0];
    // d_in[1] = path (int32, unused by the forward outputs)
    const float* fc1_w = (const float*)d_in[2];
    const float* fc1_b = (const float*)d_in[3];
    const float* fc2_w = (const float*)d_in[4];
    const float* fc2_b = (const float*)d_in[5];
    const float* fc3_w = (const float*)d_in[6];
    const float* fc3_b = (const float*)d_in[7];
    const float* pw    = (const float*)d_in[8];
    const float* pb    = (const float*)d_in[9];
    float* out = (float*)d_out;

    node2vec_kernel<<<2, 192>>>(x, fc1_w, fc1_b, fc2_w, fc2_b,
                                fc3_w, fc3_b, pw, pb, out);
}

// round 16
// speedup vs baseline: 1.0435x; 1.0435x over previous
#include <cuda_runtime.h>

// Node2VecModel: N=6, EMB=32. TWO independent CTAs (one chain per SM):
//   block 0 (192 thr): energy MLP -> out[0..5]
//   block 1 ( 64 thr of 192): raw path logits -> gumbel-max walk -> out[6..12]
// FINAL (= R13, measured best: kernel 5.152us, dur 6.656us):
//   - chain separation across 2 CTAs (no shared LSU/issue/L1tex queue)
//   - weights prefetched to registers (smem staging regressed in R5/R8/R15)
//   - x staged via scalar LDG+STS (register-x and float4 variants regressed)
//   - h1: 4-way split accumulators; h2+head fused with butterfly reduction
//   - threefry2x32 AND gumbel values baked at compile time (argmax gaps O(0.1),
//     so 1e-7-scale log differences cannot flip an index)
//   - raw-logit argmax (log_softmax row constant cancels)

#define NN   6
#define EMBD 32
#define H1   64
#define H2   32

// ---------------- compile-time threefry2x32 (partitionable JAX path) ----------------
struct TF2 { unsigned a, b; };

constexpr unsigned rotl_c(unsigned x, int r) { return (x << r) | (x >> (32 - r)); }

constexpr TF2 tf_const(unsigned k0, unsigned k1, unsigned x0, unsigned x1) {
    unsigned ks2 = k0 ^ k1 ^ 0x1BD11BDAu;
    x0 += k0; x1 += k1;
#define TFC(r) { x0 += x1; x1 = rotl_c(x1, r); x1 ^= x0; }
    TFC(13) TFC(15) TFC(26) TFC(6)
    x0 += k1;  x1 += ks2 + 1u;
    TFC(17) TFC(29) TFC(16) TFC(24)
    x0 += ks2; x1 += k0 + 2u;
    TFC(13) TFC(15) TFC(26) TFC(6)
    x0 += k0;  x1 += k1 + 3u;
    TFC(17) TFC(29) TFC(16) TFC(24)
    x0 += k1;  x1 += ks2 + 4u;
    TFC(13) TFC(15) TFC(26) TFC(6)
    x0 += ks2; x1 += k0 + 5u;
#undef TFC
    return TF2{x0, x1};
}

// split(key(42),5)[s] = tf((0,42),(0,s)); bits[j] = o0^o1 of tf(key,(0,j))
constexpr unsigned gbits(unsigned s, unsigned j) {
    TF2 key = tf_const(0u, 42u, 0u, s);
    TF2 o   = tf_const(key.a, key.b, 0u, j);
    return o.a ^ o.b;
}

// compile-time natural log (double): v = m*2^e, m in [0.5,1);
// ln(m) = 2*atanh((m-1)/(m+1)) series. |err| ~ 1e-16.
constexpr double clog(double v) {
    int e = 0;
    while (v >= 1.0) { v *= 0.5; e++; }
    while (v < 0.5)  { v *= 2.0; e--; }
    double t = (v - 1.0) / (v + 1.0);
    double t2 = t * t, term = t, sum = 0.0;
    for (int i = 1; i < 61; i += 2) { sum += term / (double)i; term *= t2; }
    return 2.0 * sum + (double)e * 0.6931471805599453;
}

// gumbel value from threefry bits, fully compile time. Matches device math:
// f = (b>>9)/2^23 (exact), u = max(tiny, f+tiny), g = -log(-log(u)).
// Gumbel gaps are O(0.1); 1e-7-scale differences cannot flip the argmax.
constexpr float gumbel_c(unsigned b) {
    const double tiny = 1.1754943508222875e-38;
    double f = (double)(b >> 9) / 8388608.0;
    double u = f + tiny;
    if (u < tiny) u = tiny;
    return (float)(-clog(-clog(u)));
}

#define GBV(s) gumbel_c(gbits(s,0)), gumbel_c(gbits(s,1)), gumbel_c(gbits(s,2)), \
               gumbel_c(gbits(s,3)), gumbel_c(gbits(s,4)), gumbel_c(gbits(s,5))
__device__ constexpr float GVAL[(NN - 1) * NN] = { GBV(0), GBV(1), GBV(2), GBV(3), GBV(4) };
#undef GBV

__global__ __launch_bounds__(192, 1)
void node2vec_kernel(const float* __restrict__ x,
                     const float* __restrict__ fc1_w, const float* __restrict__ fc1_b,
                     const float* __restrict__ fc2_w, const float* __restrict__ fc2_b,
                     const float* __restrict__ fc3_w, const float* __restrict__ fc3_b,
                     const float* __restrict__ pw,    const float* __restrict__ pb,
                     float* __restrict__ out) {
    __shared__ float sxE[NN * EMBD];         // block 0: staged x
    __shared__ float h1s[NN][H1];            // block 0: h1
    __shared__ float logits[NN][NN];         // block 1: raw logits

    int tid = threadIdx.x;

    if (blockIdx.x == 0) {
        // ================= ENERGY CTA (192 thr, own SM) =================
        int j1 = tid & 63, r1 = tid >> 6;          // h1 elems (r1,j1),(r1+3,j1)
        int i2 = tid >> 5, j2 = tid & 31;          // h2 elem (i2,j2); warp i2 = row i2

        // register prefetch: all LDGs issued before the first barrier
        float w1[EMBD];
        #pragma unroll
        for (int k = 0; k < EMBD; k++) w1[k] = fc1_w[k * H1 + j1];
        float b1v = fc1_b[j1];

        float w2[H1];
        #pragma unroll
        for (int k = 0; k < H1; k++) w2[k] = fc2_w[k * H2 + j2];
        float b2v = fc2_b[j2];
        float w3v = fc3_w[j2];
        float b3v = fc3_b[0];

        sxE[tid] = x[tid];                          // stage x (192 floats)
        __syncthreads();

        // h1 = relu(x @ fc1_w + b1): 2 rows/thread, 4-way split accumulators
        // (shorter dependent-FMA chain; fp32 reorder ~1e-7, threshold 1e-3)
        {
            float p0 = 0.f, p1 = 0.f, p2 = 0.f, p3 = 0.f;
            float q0 = 0.f, q1 = 0.f, q2 = 0.f, q3 = 0.f;
            #pragma unroll
            for (int k = 0; k < EMBD; k += 4) {
                p0 += sxE[r1 * EMBD + k]     * w1[k];
                p1 += sxE[r1 * EMBD + k + 1] * w1[k + 1];
                p2 += sxE[r1 * EMBD + k + 2] * w1[k + 2];
                p3 += sxE[r1 * EMBD + k + 3] * w1[k + 3];
                q0 += sxE[(r1 + 3) * EMBD + k]     * w1[k];
                q1 += sxE[(r1 + 3) * EMBD + k + 1] * w1[k + 1];
                q2 += sxE[(r1 + 3) * EMBD + k + 2] * w1[k + 2];
                q3 += sxE[(r1 + 3) * EMBD + k + 3] * w1[k + 3];
            }
            h1s[r1][j1]     = fmaxf(b1v + ((p0 + p1) + (p2 + p3)), 0.0f);
            h1s[r1 + 3][j1] = fmaxf(b1v + ((q0 + q1) + (q2 + q3)), 0.0f);
        }
        __syncthreads();

        // h2 + energy head fused: warp i2 owns row i2; lane j2 computes h2[i2][j2],
        // scales by fc3_w[j2], warp-reduces, lane 0 applies softplus and stores.
        {
            float c0 = 0.f, c1 = 0.f, c2 = 0.f, c3 = 0.f;
            #pragma unroll
            for (int k = 0; k < H1; k += 4) {
                c0 += h1s[i2][k]     * w2[k];
                c1 += h1s[i2][k + 1] * w2[k + 1];
                c2 += h1s[i2][k + 2] * w2[k + 2];
                c3 += h1s[i2][k + 3] * w2[k + 3];
            }
            float rel = fmaxf(b2v + ((c0 + c1) + (c2 + c3)), 0.0f);
            float p = rel * w3v;
            #pragma unroll
            for (int off = 16; off; off >>= 1)
                p += __shfl_xor_sync(0xffffffffu, p, off);
            if (j2 == 0) {
                float acc = p + b3v;
                out[i2] = fmaxf(acc, 0.0f) + log1pf(expf(-fabsf(acc)));  // softplus
            }
        }
    } else {
        // ================= PATH CTA (uses 64 of 192 thr, own SM) =================
        if (tid >= 64) return;
        int t = tid;

        // fixed endpoints: write early from an otherwise-idle thread
        if (t == 40) { out[NN] = 0.0f; out[2 * NN] = 0.0f; }

        // raw logits = x @ path_fc_w + path_fc_b (36 threads) — LDG-bound.
        // log_softmax skipped: per-row constant cancels in the argmax below.
        if (t < NN * NN) {
            int i = t / NN, j = t % NN;
            float acc = pb[j];
            #pragma unroll
            for (int k = 0; k < EMBD; k++)
                acc += x[i * EMBD + k] * pw[k * NN + j];
            logits[i][j] = acc;
        }
        asm volatile("bar.sync 2, 64;" ::: "memory");

        // serial gumbel-max walk (thread 0): gumbels are immediates,
        // per step just 6 LDS + compares.
        if (t == 0) {
            bool mask[NN];
            mask[0] = false;
            #pragma unroll
            for (int j = 1; j < NN; j++) mask[j] = true;

            int cur = 0;
            #pragma unroll
            for (int step = 0; step < NN - 1; step++) {
                float best = -__int_as_float(0x7f800000);
                int bestj = 0;
                bool have = false;
                #pragma unroll
                for (int j = 0; j < NN; j++) {
                    if (!mask[j]) continue;          // where(mask,.,-inf)+g = -inf
                    float v = logits[cur][j] + GVAL[step * NN + j];
                    if (!have || v > best) { best = v; bestj = j; have = true; }
                }
                cur = bestj;
                mask[bestj] = false;
                out[NN + 1 + step] = (float)bestj;
            }
        }
    }
}

extern "C" void kernel_launch(void* const* d_in, const int* in_sizes, int n_in,
                              void* d_out, int out_size) {
    const float* x     = (const float*)d_in[0];
    // d_in[1] = path (int32, unused by the forward outputs)
    const float* fc1_w = (const float*)d_in[2];
    const float* fc1_b = (const float*)d_in[3];
    const float* fc2_w = (const float*)d_in[4];
    const float* fc2_b = (const float*)d_in[5];
    const float* fc3_w = (const float*)d_in[6];
    const float* fc3_b = (const float*)d_in[7];
    const float* pw    = (const float*)d_in[8];
    const float* pb    = (const float*)d_in[9];
    float* out = (float*)d_out;

    node2vec_kernel<<<2, 192>>>(x, fc1_w, fc1_b, fc2_w, fc2_b,
                                fc3_w, fc3_b, pw, pb, out);
}